// round 13
// baseline (speedup 1.0000x reference)
#include <cuda_runtime.h>
#include <cstdint>

#define NB 128
#define HH 40
#define WW 40
#define HW 1600
#define NC 16
#define NS 32
#define NTHREADS 384
#define FRAME (NB*HW*NC)
#define RGBFRAME (NB*HW*3)
#define NFRAMES (NS+1)

typedef unsigned long long u64;

__device__ float g_stA[FRAME];
__device__ float g_stB[FRAME];

// ---------------- packed f32x2 helpers ----------------
__device__ __forceinline__ u64 pk2(float lo, float hi) {
    u64 r; asm("mov.b64 %0, {%1, %2};" : "=l"(r) : "f"(lo), "f"(hi)); return r;
}
__device__ __forceinline__ float2 upk2(u64 v) {
    float2 r; asm("mov.b64 {%0, %1}, %2;" : "=f"(r.x), "=f"(r.y) : "l"(v)); return r;
}
__device__ __forceinline__ u64 fma2(u64 a, u64 b, u64 c) {
    u64 d; asm("fma.rn.f32x2 %0, %1, %2, %3;" : "=l"(d) : "l"(a), "l"(b), "l"(c)); return d;
}
__device__ __forceinline__ u64 mul2(u64 a, u64 b) {
    u64 d; asm("mul.rn.f32x2 %0, %1, %2;" : "=l"(d) : "l"(a), "l"(b)); return d;
}

// ---------------- explicit shared-memory access ----------------
__device__ __forceinline__ void lds_v2(uint32_t a, u64& x, u64& y) {
    asm volatile("ld.shared.v2.u64 {%0, %1}, [%2];" : "=l"(x), "=l"(y) : "r"(a));
}
__device__ __forceinline__ u64 lds_u64(uint32_t a) {
    u64 x; asm volatile("ld.shared.u64 %0, [%1];" : "=l"(x) : "r"(a)); return x;
}
__device__ __forceinline__ float lds_f32(uint32_t a) {
    float x; asm volatile("ld.shared.f32 %0, [%1];" : "=f"(x) : "r"(a)); return x;
}
__device__ __forceinline__ float4 lds_v4f(uint32_t a) {
    float4 v;
    asm volatile("ld.shared.v4.f32 {%0, %1, %2, %3}, [%4];"
                 : "=f"(v.x), "=f"(v.y), "=f"(v.z), "=f"(v.w) : "r"(a));
    return v;
}
__device__ __forceinline__ void sts_f32(uint32_t a, float v) {
    asm volatile("st.shared.f32 [%0], %1;" :: "r"(a), "f"(v));
}
__device__ __forceinline__ void sts_v4(uint32_t a, float4 v) {
    asm volatile("st.shared.v4.f32 [%0], {%1, %2, %3, %4};"
                 :: "r"(a), "f"(v.x), "f"(v.y), "f"(v.z), "f"(v.w));
}

// ---------------- rgb emit ----------------
__device__ __forceinline__ void emit_rgb(unsigned char* rgb8, float* rgbf,
                                         int idx3, float r, float g, float b, float a) {
    float ac = fminf(fmaxf(a, 0.f), 1.f);
    unsigned char ur = (unsigned char)(fminf(fmaxf(1.f - ac + r, 0.f), 1.f) * 255.f);
    unsigned char ug = (unsigned char)(fminf(fmaxf(1.f - ac + g, 0.f), 1.f) * 255.f);
    unsigned char ub = (unsigned char)(fminf(fmaxf(1.f - ac + b, 0.f), 1.f) * 255.f);
    if (rgb8) { rgb8[idx3] = ur; rgb8[idx3+1] = ug; rgb8[idx3+2] = ub; }
    if (rgbf) { rgbf[idx3] = (float)ur; rgbf[idx3+1] = (float)ug; rgbf[idx3+2] = (float)ub; }
}

// SMEM byte offsets
#define SP_OFF    0          // state AoS, [1600] x 80B (16 floats + 4 pad)
#define AL_OFF    128000     // current masked alpha [1600]
#define AM_OFF    134400     // alive mask [1600]
#define ALN_OFF   140800     // new alpha (pre-mask) [1600]
#define W1_OFF    147200     // [128][48]
#define W2_OFF    171776     // [128][16] transposed
#define B1_OFF    179968     // [128] u64 pairs (b1, 0)
#define CNT_OFF   180992     // int counter
#define LIST_OFF  181000     // u16[1600] active pixel list
#define SMEM_BYTES 184320

// ---------------- fused perception + MLP for PX active pixels ----------------
// Per-pixel arithmetic EXACTLY R1/R3/R9/R12:
//   acc = (b1,0); 24 sequential fma2 over pairs 0..23; hid = relu(acc.x+acc.y)
//   upd2[cp] accumulated in o order 0..127; writeback fma2(upd, 1, state)
template<int PX>
__device__ __forceinline__ void mlp_pixels(
    uint32_t smb, float* __restrict__ gdst, int pix0, int pix1)
{
    const float twx[8] = {-0.125f, 0.f, 0.125f, -0.25f, 0.25f, -0.125f, 0.f, 0.125f};
    const float twy[8] = {-0.125f, -0.25f, -0.125f, 0.f, 0.f, 0.125f, 0.25f, 0.125f};
    const int   tdh[8] = {-1,-1,-1, 0, 0, 1, 1, 1};
    const int   tdw[8] = {-1, 0, 1,-1, 1,-1, 0, 1};

    int pix[2]; pix[0] = pix0; pix[1] = pix1;

    // perception: pp[0..7]=masked, [8..15]=sx, [16..23]=sy (pairs of channels)
    u64 pp[PX][24];
    #pragma unroll
    for (int q = 0; q < PX; q++) {
        int p = pix[q];
        int h = p / WW, w = p % WW;
        float amc = lds_f32(smb + AM_OFF + p*4);
        u64 amc2 = pk2(amc, amc);
        uint32_t ra = smb + SP_OFF + p*80;
        #pragma unroll
        for (int j = 0; j < 4; j++) {
            u64 a, b; lds_v2(ra + j*16, a, b);
            pp[q][2*j]   = mul2(a, amc2);
            pp[q][2*j+1] = mul2(b, amc2);
        }
        #pragma unroll
        for (int j = 8; j < 24; j++) pp[q][j] = 0ull;

        #pragma unroll
        for (int t = 0; t < 8; t++) {
            int nh = h + tdh[t], nw = w + tdw[t];
            if ((unsigned)nh < (unsigned)HH && (unsigned)nw < (unsigned)WW) {
                int n = nh * WW + nw;
                float amn = lds_f32(smb + AM_OFF + n*4);
                u64 amn2 = pk2(amn, amn);
                u64 wx2 = pk2(twx[t], twx[t]);
                u64 wy2 = pk2(twy[t], twy[t]);
                uint32_t na = smb + SP_OFF + n*80;
                #pragma unroll
                for (int j = 0; j < 4; j++) {
                    u64 a, b; lds_v2(na + j*16, a, b);
                    u64 m0 = mul2(a, amn2), m1 = mul2(b, amn2);
                    pp[q][8+2*j]    = fma2(wx2, m0, pp[q][8+2*j]);
                    pp[q][8+2*j+1]  = fma2(wx2, m1, pp[q][8+2*j+1]);
                    pp[q][16+2*j]   = fma2(wy2, m0, pp[q][16+2*j]);
                    pp[q][16+2*j+1] = fma2(wy2, m1, pp[q][16+2*j+1]);
                }
            }
        }
    }

    u64 upd2[PX][8];
    #pragma unroll
    for (int q = 0; q < PX; q++)
        #pragma unroll
        for (int j = 0; j < 8; j++) upd2[q][j] = 0ull;

    #pragma unroll 4
    for (int o = 0; o < 128; o++) {
        uint32_t wa = smb + W1_OFF + o*192;
        u64 b1p = lds_u64(smb + B1_OFF + o*8);
        u64 acc[PX];
        #pragma unroll
        for (int q = 0; q < PX; q++) acc[q] = b1p;
        // single sequential chain per pixel — R1 order: pairs 0..23
        #pragma unroll
        for (int j = 0; j < 12; j++) {
            u64 w0, w1; lds_v2(wa + j*16, w0, w1);
            #pragma unroll
            for (int q = 0; q < PX; q++) {
                acc[q] = fma2(w0, pp[q][2*j],   acc[q]);
                acc[q] = fma2(w1, pp[q][2*j+1], acc[q]);
            }
        }
        u64 w2r[8];
        lds_v2(smb + W2_OFF + o*64,      w2r[0], w2r[1]);
        lds_v2(smb + W2_OFF + o*64 + 16, w2r[2], w2r[3]);
        lds_v2(smb + W2_OFF + o*64 + 32, w2r[4], w2r[5]);
        lds_v2(smb + W2_OFF + o*64 + 48, w2r[6], w2r[7]);
        #pragma unroll
        for (int q = 0; q < PX; q++) {
            float2 ah = upk2(acc[q]);
            float hid = fmaxf(ah.x + ah.y, 0.f);
            u64 h2 = pk2(hid, hid);
            #pragma unroll
            for (int cp = 0; cp < 8; cp++)
                upd2[q][cp] = fma2(w2r[cp], h2, upd2[q][cp]);
        }
    }

    // writeback pre-mask state to gdst; stash new alpha in smem
    u64 one2 = pk2(1.0f, 1.0f);
    #pragma unroll
    for (int q = 0; q < PX; q++) {
        int p = pix[q];
        uint32_t ra = smb + SP_OFF + p*80;
        float nv[16];
        #pragma unroll
        for (int j = 0; j < 4; j++) {
            u64 a, b; lds_v2(ra + j*16, a, b);
            u64 n0 = fma2(upd2[q][2*j],   one2, a);
            u64 n1 = fma2(upd2[q][2*j+1], one2, b);
            float2 f0 = upk2(n0), f1 = upk2(n1);
            nv[4*j] = f0.x; nv[4*j+1] = f0.y; nv[4*j+2] = f1.x; nv[4*j+3] = f1.y;
        }
        sts_f32(smb + ALN_OFF + p*4, nv[3]);
        float4* o4 = (float4*)(gdst + (size_t)p * NC);
        o4[0] = make_float4(nv[0],  nv[1],  nv[2],  nv[3]);
        o4[1] = make_float4(nv[4],  nv[5],  nv[6],  nv[7]);
        o4[2] = make_float4(nv[8],  nv[9],  nv[10], nv[11]);
        o4[3] = make_float4(nv[12], nv[13], nv[14], nv[15]);
    }
}

// ---------------- persistent kernel: one CTA per image, all 32 steps ----------
__global__ void __launch_bounds__(NTHREADS, 1) nca_persist(
    const float* __restrict__ initial,
    float* __restrict__ stacked,        // may be null
    float* __restrict__ stA,
    float* __restrict__ stB,
    const float* __restrict__ gW1,
    const float* __restrict__ gb1,
    const float* __restrict__ gW2,
    const int*  __restrict__ gupd,
    unsigned char* rgb8, float* rgbf)
{
    extern __shared__ float sm[];
    uint32_t smb;
    asm("{ .reg .u64 t; cvta.to.shared.u64 t, %1; cvt.u32.u64 %0, t; }"
        : "=r"(smb) : "l"(sm));
    int* cnt = (int*)((char*)sm + CNT_OFF);
    unsigned short* list = (unsigned short*)((char*)sm + LIST_OFF);

    const int b   = blockIdx.x;
    const int tid = threadIdx.x;

    // ---- weights once ----
    for (int i = tid; i < 6144/4; i += NTHREADS)
        sts_v4(smb + W1_OFF + i*16, ((const float4*)gW1)[i]);
    if (tid < 128) {
        sts_f32(smb + B1_OFF + tid*8,     gb1[tid]);
        sts_f32(smb + B1_OFF + tid*8 + 4, 0.f);
    }
    for (int i = tid; i < 2048; i += NTHREADS) {
        int c = i >> 7, o = i & 127;
        sts_f32(smb + W2_OFF + (o*16 + c)*4, gW2[i]);
    }
    if (tid == 0) cnt[0] = 0;

    // ---- frame 0: initial -> SP + AL + gdst0 + rgb0 ----
    {
        const float* gsrc = initial + (size_t)b * HW * NC;
        float* dst0 = (stacked ? stacked : stA) + (size_t)b * HW * NC;
        for (int i = tid; i < HW*NC/4; i += NTHREADS) {
            int pix = i >> 2, q = i & 3;
            float4 v = ((const float4*)gsrc)[i];
            sts_v4(smb + SP_OFF + pix*80 + q*16, v);
            ((float4*)(dst0 + (size_t)pix * NC))[q] = v;
            if (q == 0) {
                sts_f32(smb + AL_OFF + pix*4, v.w);
                if (rgb8 || rgbf)
                    emit_rgb(rgb8, rgbf, (b*HW + pix)*3, v.x, v.y, v.z, v.w);
            }
        }
    }
    __syncthreads();

    // ---- 32 steps ----
    #pragma unroll 1
    for (int s = 0; s < NS; s++) {
        float* gdst = (stacked ? stacked + (size_t)(s+1) * FRAME
                               : ((s & 1) ? stA : stB)) + (size_t)b * HW * NC;
        const int* updrow = gupd + (size_t)s * NB * HW + b * HW;
        unsigned char* r8 = rgb8 ? rgb8 + (size_t)(s+1) * RGBFRAME : nullptr;
        float* rf = rgbf ? rgbf + (size_t)(s+1) * RGBFRAME : nullptr;

        // fused phase: alive mask (AM = f(AL)) + compaction (active list /
        // inactive copy SP -> gdst + ALN). cnt[0] reset before prior barrier.
        {
            int myact[5], nact = 0;   // ceil(1600/384) = 5 slots
            for (int p = tid; p < HW; p += NTHREADS) {
                int h = p / WW, w = p % WW;
                float m = -1e30f;
                #pragma unroll
                for (int dh = -1; dh <= 1; dh++) {
                    int nh = h + dh;
                    if ((unsigned)nh >= (unsigned)HH) continue;
                    #pragma unroll
                    for (int dw = -1; dw <= 1; dw++) {
                        int nw = w + dw;
                        if ((unsigned)nw >= (unsigned)WW) continue;
                        m = fmaxf(m, lds_f32(smb + AL_OFF + (nh*WW + nw)*4));
                    }
                }
                sts_f32(smb + AM_OFF + p*4, (m >= 0.1f) ? 1.0f : 0.0f);

                if (updrow[p] != 0) {
                    myact[nact++] = p;
                } else {
                    uint32_t ra = smb + SP_OFF + p*80;
                    float4* o4 = (float4*)(gdst + (size_t)p * NC);
                    #pragma unroll
                    for (int j = 0; j < 4; j++) {
                        u64 a, bb; lds_v2(ra + j*16, a, bb);
                        float2 f0 = upk2(a), f1 = upk2(bb);
                        o4[j] = make_float4(f0.x, f0.y, f1.x, f1.y);
                        if (j == 0) sts_f32(smb + ALN_OFF + p*4, f1.y);
                    }
                }
            }
            int pos = atomicAdd(cnt, nact);
            for (int i = 0; i < nact; i++) list[pos + i] = (unsigned short)myact[i];
        }
        __syncthreads();

        int A = cnt[0];

        if (A > 0) {
            // wave 1: inline clamp instead of list padding (no extra barrier)
            int i0 = 2*tid, i1 = 2*tid + 1;
            int p0 = (i0 < A) ? (int)list[i0] : (int)list[0];
            int p1 = (i1 < A) ? (int)list[i1] : (int)list[0];
            mlp_pixels<2>(smb, gdst, p0, p1);
            // tail: leftover (A > 768) as singles
            #pragma unroll 1
            for (int i = 2*NTHREADS + tid; i < A; i += NTHREADS)
                mlp_pixels<1>(smb, gdst, (int)list[i], (int)list[i]);
        }
        __syncthreads();

        // phase 2: alive mask on new alpha; finalize gdst + SP + AL + rgb.
        // Active pixels' pre-mask state loads hoisted above the 9-LDS max.
        for (int pix = tid; pix < HW; pix += NTHREADS) {
            bool act = (updrow[pix] != 0);
            uint32_t ra = smb + SP_OFF + pix*80;

            float4 g0, g1, g2, g3;
            if (act) {
                // issue early: L2 latency hidden under the alive-max chain
                const float4* g4 = (const float4*)(gdst + (size_t)pix * NC);
                g0 = g4[0]; g1 = g4[1]; g2 = g4[2]; g3 = g4[3];
            }

            int h = pix / WW, w = pix % WW;
            float m = -1e30f;
            #pragma unroll
            for (int dh = -1; dh <= 1; dh++) {
                int nh = h + dh;
                if ((unsigned)nh >= (unsigned)HH) continue;
                #pragma unroll
                for (int dw = -1; dw <= 1; dw++) {
                    int nw = w + dw;
                    if ((unsigned)nw >= (unsigned)WW) continue;
                    m = fmaxf(m, lds_f32(smb + ALN_OFF + (nh*WW + nw)*4));
                }
            }
            bool alive = (m >= 0.1f);

            float4 q0;
            if (alive) {
                if (act) {
                    q0 = g0;
                    sts_v4(ra,      g0);
                    sts_v4(ra + 16, g1);
                    sts_v4(ra + 32, g2);
                    sts_v4(ra + 48, g3);
                } else {
                    q0 = lds_v4f(ra);
                }
            } else {
                q0 = make_float4(0.f, 0.f, 0.f, 0.f);
                float4* o4 = (float4*)(gdst + (size_t)pix * NC);
                o4[0] = q0; o4[1] = q0; o4[2] = q0; o4[3] = q0;
                sts_v4(ra,      q0);
                sts_v4(ra + 16, q0);
                sts_v4(ra + 32, q0);
                sts_v4(ra + 48, q0);
            }
            sts_f32(smb + AL_OFF + pix*4, q0.w);
            if (rgb8 || rgbf)
                emit_rgb(r8, rf, (b*HW + pix)*3, q0.x, q0.y, q0.z, q0.w);
        }
        if (tid == 0) cnt[0] = 0;   // reset for next step, before the barrier
        __syncthreads();
    }
}

// ---------------- launch ----------------
extern "C" void kernel_launch(void* const* d_in, const int* in_sizes, int n_in,
                              void* d_out, int out_size) {
    const float* initial = (const float*)d_in[0];
    const float* W1 = (const float*)d_in[1];
    const float* b1 = (const float*)d_in[2];
    const float* W2 = (const float*)d_in[3];
    const int*  upd = (const int*)d_in[4];

    const long long NTOT = (long long)NFRAMES * NB * HW;
    const long long RGB_N = 3 * NTOT;
    const long long STK_N = 16 * NTOT;

    float* stacked = nullptr;
    unsigned char* rgb8 = nullptr;
    float* rgbf = nullptr;

    long long osz = (long long)out_size;
    if (osz >= RGB_N + 4*STK_N) {
        rgb8 = (unsigned char*)d_out;
        stacked = (float*)((char*)d_out + RGB_N);
    } else if (osz >= RGB_N + STK_N) {
        rgbf = (float*)d_out;
        stacked = (float*)d_out + RGB_N;
    } else if (osz >= STK_N) {
        stacked = (float*)d_out;
    } else if (osz >= RGB_N) {
        rgb8 = (unsigned char*)d_out;
    }

    float* stA = nullptr;
    float* stB = nullptr;
    if (!stacked) {
        cudaGetSymbolAddress((void**)&stA, g_stA);
        cudaGetSymbolAddress((void**)&stB, g_stB);
    }

    cudaFuncSetAttribute(nca_persist, cudaFuncAttributeMaxDynamicSharedMemorySize, SMEM_BYTES);

    nca_persist<<<NB, NTHREADS, SMEM_BYTES>>>(initial, stacked, stA, stB,
                                              W1, b1, W2, upd, rgb8, rgbf);
}

// round 14
// speedup vs baseline: 1.0338x; 1.0338x over previous
#include <cuda_runtime.h>
#include <cstdint>

#define NB 128
#define HH 40
#define WW 40
#define HW 1600
#define NC 16
#define NS 32
#define NTHREADS 384
#define FRAME (NB*HW*NC)
#define RGBFRAME (NB*HW*3)
#define NFRAMES (NS+1)

typedef unsigned long long u64;

__device__ float g_stA[FRAME];
__device__ float g_stB[FRAME];

// ---------------- packed f32x2 helpers ----------------
__device__ __forceinline__ u64 pk2(float lo, float hi) {
    u64 r; asm("mov.b64 %0, {%1, %2};" : "=l"(r) : "f"(lo), "f"(hi)); return r;
}
__device__ __forceinline__ float2 upk2(u64 v) {
    float2 r; asm("mov.b64 {%0, %1}, %2;" : "=f"(r.x), "=f"(r.y) : "l"(v)); return r;
}
__device__ __forceinline__ u64 fma2(u64 a, u64 b, u64 c) {
    u64 d; asm("fma.rn.f32x2 %0, %1, %2, %3;" : "=l"(d) : "l"(a), "l"(b), "l"(c)); return d;
}
__device__ __forceinline__ u64 mul2(u64 a, u64 b) {
    u64 d; asm("mul.rn.f32x2 %0, %1, %2;" : "=l"(d) : "l"(a), "l"(b)); return d;
}

// ---------------- explicit shared-memory access ----------------
__device__ __forceinline__ void lds_v2(uint32_t a, u64& x, u64& y) {
    asm volatile("ld.shared.v2.u64 {%0, %1}, [%2];" : "=l"(x), "=l"(y) : "r"(a));
}
__device__ __forceinline__ u64 lds_u64(uint32_t a) {
    u64 x; asm volatile("ld.shared.u64 %0, [%1];" : "=l"(x) : "r"(a)); return x;
}
__device__ __forceinline__ float lds_f32(uint32_t a) {
    float x; asm volatile("ld.shared.f32 %0, [%1];" : "=f"(x) : "r"(a)); return x;
}
__device__ __forceinline__ float4 lds_v4f(uint32_t a) {
    float4 v;
    asm volatile("ld.shared.v4.f32 {%0, %1, %2, %3}, [%4];"
                 : "=f"(v.x), "=f"(v.y), "=f"(v.z), "=f"(v.w) : "r"(a));
    return v;
}
__device__ __forceinline__ void sts_f32(uint32_t a, float v) {
    asm volatile("st.shared.f32 [%0], %1;" :: "r"(a), "f"(v));
}
__device__ __forceinline__ void sts_v4(uint32_t a, float4 v) {
    asm volatile("st.shared.v4.f32 [%0], {%1, %2, %3, %4};"
                 :: "r"(a), "f"(v.x), "f"(v.y), "f"(v.z), "f"(v.w));
}

// ---------------- rgb emit ----------------
__device__ __forceinline__ void emit_rgb(unsigned char* rgb8, float* rgbf,
                                         int idx3, float r, float g, float b, float a) {
    float ac = fminf(fmaxf(a, 0.f), 1.f);
    unsigned char ur = (unsigned char)(fminf(fmaxf(1.f - ac + r, 0.f), 1.f) * 255.f);
    unsigned char ug = (unsigned char)(fminf(fmaxf(1.f - ac + g, 0.f), 1.f) * 255.f);
    unsigned char ub = (unsigned char)(fminf(fmaxf(1.f - ac + b, 0.f), 1.f) * 255.f);
    if (rgb8) { rgb8[idx3] = ur; rgb8[idx3+1] = ug; rgb8[idx3+2] = ub; }
    if (rgbf) { rgbf[idx3] = (float)ur; rgbf[idx3+1] = (float)ug; rgbf[idx3+2] = (float)ub; }
}

// SMEM byte offsets
#define SP_OFF    0          // state AoS, [1600] x 80B (16 floats + 4 pad)
#define AL_OFF    128000     // current masked alpha [1600]
#define AM_OFF    134400     // alive mask [1600]
#define ALN_OFF   140800     // new alpha (pre-mask) [1600]
#define W1_OFF    147200     // [128][48]
#define W2_OFF    171776     // [128][16] transposed
#define B1_OFF    179968     // [128] u64 pairs (b1, 0)
#define CNT_OFF   180992     // int counter
#define LIST_OFF  181000     // u16[1600] active pixel list
#define SMEM_BYTES 184320

// ---------------- fused perception + MLP for PX active pixels ----------------
// Per-pixel arithmetic EXACTLY R1/R3/R9/R12:
//   acc = (b1,0); 24 sequential fma2 over pairs 0..23; hid = relu(acc.x+acc.y)
//   upd2[cp] accumulated in o order 0..127; writeback fma2(upd, 1, state)
template<int PX>
__device__ __forceinline__ void mlp_pixels(
    uint32_t smb, float* __restrict__ gdst, int pix0, int pix1)
{
    const float twx[8] = {-0.125f, 0.f, 0.125f, -0.25f, 0.25f, -0.125f, 0.f, 0.125f};
    const float twy[8] = {-0.125f, -0.25f, -0.125f, 0.f, 0.f, 0.125f, 0.25f, 0.125f};
    const int   tdh[8] = {-1,-1,-1, 0, 0, 1, 1, 1};
    const int   tdw[8] = {-1, 0, 1,-1, 1,-1, 0, 1};

    int pix[2]; pix[0] = pix0; pix[1] = pix1;

    // perception: pp[0..7]=masked, [8..15]=sx, [16..23]=sy (pairs of channels)
    u64 pp[PX][24];
    #pragma unroll
    for (int q = 0; q < PX; q++) {
        int p = pix[q];
        int h = p / WW, w = p % WW;
        float amc = lds_f32(smb + AM_OFF + p*4);
        u64 amc2 = pk2(amc, amc);
        uint32_t ra = smb + SP_OFF + p*80;
        #pragma unroll
        for (int j = 0; j < 4; j++) {
            u64 a, b; lds_v2(ra + j*16, a, b);
            pp[q][2*j]   = mul2(a, amc2);
            pp[q][2*j+1] = mul2(b, amc2);
        }
        #pragma unroll
        for (int j = 8; j < 24; j++) pp[q][j] = 0ull;

        #pragma unroll
        for (int t = 0; t < 8; t++) {
            int nh = h + tdh[t], nw = w + tdw[t];
            if ((unsigned)nh < (unsigned)HH && (unsigned)nw < (unsigned)WW) {
                int n = nh * WW + nw;
                float amn = lds_f32(smb + AM_OFF + n*4);
                u64 amn2 = pk2(amn, amn);
                u64 wx2 = pk2(twx[t], twx[t]);
                u64 wy2 = pk2(twy[t], twy[t]);
                uint32_t na = smb + SP_OFF + n*80;
                #pragma unroll
                for (int j = 0; j < 4; j++) {
                    u64 a, b; lds_v2(na + j*16, a, b);
                    u64 m0 = mul2(a, amn2), m1 = mul2(b, amn2);
                    pp[q][8+2*j]    = fma2(wx2, m0, pp[q][8+2*j]);
                    pp[q][8+2*j+1]  = fma2(wx2, m1, pp[q][8+2*j+1]);
                    pp[q][16+2*j]   = fma2(wy2, m0, pp[q][16+2*j]);
                    pp[q][16+2*j+1] = fma2(wy2, m1, pp[q][16+2*j+1]);
                }
            }
        }
    }

    u64 upd2[PX][8];
    #pragma unroll
    for (int q = 0; q < PX; q++)
        #pragma unroll
        for (int j = 0; j < 8; j++) upd2[q][j] = 0ull;

    #pragma unroll 2
    for (int o = 0; o < 128; o++) {
        uint32_t wa = smb + W1_OFF + o*192;
        u64 b1p = lds_u64(smb + B1_OFF + o*8);
        u64 acc[PX];
        #pragma unroll
        for (int q = 0; q < PX; q++) acc[q] = b1p;
        // single sequential chain per pixel — R1 order: pairs 0..23
        #pragma unroll
        for (int j = 0; j < 12; j++) {
            u64 w0, w1; lds_v2(wa + j*16, w0, w1);
            #pragma unroll
            for (int q = 0; q < PX; q++) {
                acc[q] = fma2(w0, pp[q][2*j],   acc[q]);
                acc[q] = fma2(w1, pp[q][2*j+1], acc[q]);
            }
        }
        u64 w2r[8];
        lds_v2(smb + W2_OFF + o*64,      w2r[0], w2r[1]);
        lds_v2(smb + W2_OFF + o*64 + 16, w2r[2], w2r[3]);
        lds_v2(smb + W2_OFF + o*64 + 32, w2r[4], w2r[5]);
        lds_v2(smb + W2_OFF + o*64 + 48, w2r[6], w2r[7]);
        #pragma unroll
        for (int q = 0; q < PX; q++) {
            float2 ah = upk2(acc[q]);
            float hid = fmaxf(ah.x + ah.y, 0.f);
            u64 h2 = pk2(hid, hid);
            #pragma unroll
            for (int cp = 0; cp < 8; cp++)
                upd2[q][cp] = fma2(w2r[cp], h2, upd2[q][cp]);
        }
    }

    // writeback pre-mask state to gdst; stash new alpha in smem
    u64 one2 = pk2(1.0f, 1.0f);
    #pragma unroll
    for (int q = 0; q < PX; q++) {
        int p = pix[q];
        uint32_t ra = smb + SP_OFF + p*80;
        float nv[16];
        #pragma unroll
        for (int j = 0; j < 4; j++) {
            u64 a, b; lds_v2(ra + j*16, a, b);
            u64 n0 = fma2(upd2[q][2*j],   one2, a);
            u64 n1 = fma2(upd2[q][2*j+1], one2, b);
            float2 f0 = upk2(n0), f1 = upk2(n1);
            nv[4*j] = f0.x; nv[4*j+1] = f0.y; nv[4*j+2] = f1.x; nv[4*j+3] = f1.y;
        }
        sts_f32(smb + ALN_OFF + p*4, nv[3]);
        float4* o4 = (float4*)(gdst + (size_t)p * NC);
        o4[0] = make_float4(nv[0],  nv[1],  nv[2],  nv[3]);
        o4[1] = make_float4(nv[4],  nv[5],  nv[6],  nv[7]);
        o4[2] = make_float4(nv[8],  nv[9],  nv[10], nv[11]);
        o4[3] = make_float4(nv[12], nv[13], nv[14], nv[15]);
    }
}

// ---------------- persistent kernel: one CTA per image, all 32 steps ----------
__global__ void __launch_bounds__(NTHREADS, 1) nca_persist(
    const float* __restrict__ initial,
    float* __restrict__ stacked,        // may be null
    float* __restrict__ stA,
    float* __restrict__ stB,
    const float* __restrict__ gW1,
    const float* __restrict__ gb1,
    const float* __restrict__ gW2,
    const int*  __restrict__ gupd,
    unsigned char* rgb8, float* rgbf)
{
    extern __shared__ float sm[];
    uint32_t smb;
    asm("{ .reg .u64 t; cvta.to.shared.u64 t, %1; cvt.u32.u64 %0, t; }"
        : "=r"(smb) : "l"(sm));
    int* cnt = (int*)((char*)sm + CNT_OFF);
    unsigned short* list = (unsigned short*)((char*)sm + LIST_OFF);

    const int b   = blockIdx.x;
    const int tid = threadIdx.x;

    // ---- weights once ----
    for (int i = tid; i < 6144/4; i += NTHREADS)
        sts_v4(smb + W1_OFF + i*16, ((const float4*)gW1)[i]);
    if (tid < 128) {
        sts_f32(smb + B1_OFF + tid*8,     gb1[tid]);
        sts_f32(smb + B1_OFF + tid*8 + 4, 0.f);
    }
    for (int i = tid; i < 2048; i += NTHREADS) {
        int c = i >> 7, o = i & 127;
        sts_f32(smb + W2_OFF + (o*16 + c)*4, gW2[i]);
    }
    if (tid == 0) cnt[0] = 0;

    // ---- frame 0: initial -> SP + AL + gdst0 + rgb0 ----
    {
        const float* gsrc = initial + (size_t)b * HW * NC;
        float* dst0 = (stacked ? stacked : stA) + (size_t)b * HW * NC;
        for (int i = tid; i < HW*NC/4; i += NTHREADS) {
            int pix = i >> 2, q = i & 3;
            float4 v = ((const float4*)gsrc)[i];
            sts_v4(smb + SP_OFF + pix*80 + q*16, v);
            ((float4*)(dst0 + (size_t)pix * NC))[q] = v;
            if (q == 0) {
                sts_f32(smb + AL_OFF + pix*4, v.w);
                if (rgb8 || rgbf)
                    emit_rgb(rgb8, rgbf, (b*HW + pix)*3, v.x, v.y, v.z, v.w);
            }
        }
    }
    __syncthreads();

    // ---- 32 steps ----
    #pragma unroll 1
    for (int s = 0; s < NS; s++) {
        float* gdst = (stacked ? stacked + (size_t)(s+1) * FRAME
                               : ((s & 1) ? stA : stB)) + (size_t)b * HW * NC;
        const int* updrow = gupd + (size_t)s * NB * HW + b * HW;
        unsigned char* r8 = rgb8 ? rgb8 + (size_t)(s+1) * RGBFRAME : nullptr;
        float* rf = rgbf ? rgbf + (size_t)(s+1) * RGBFRAME : nullptr;

        // fused phase: alive mask (AM = f(AL)) + compaction (active list /
        // inactive copy SP -> gdst + ALN). cnt[0] reset before prior barrier.
        {
            int myact[5], nact = 0;   // ceil(1600/384) = 5 slots
            for (int p = tid; p < HW; p += NTHREADS) {
                int h = p / WW, w = p % WW;
                float m = -1e30f;
                #pragma unroll
                for (int dh = -1; dh <= 1; dh++) {
                    int nh = h + dh;
                    if ((unsigned)nh >= (unsigned)HH) continue;
                    #pragma unroll
                    for (int dw = -1; dw <= 1; dw++) {
                        int nw = w + dw;
                        if ((unsigned)nw >= (unsigned)WW) continue;
                        m = fmaxf(m, lds_f32(smb + AL_OFF + (nh*WW + nw)*4));
                    }
                }
                sts_f32(smb + AM_OFF + p*4, (m >= 0.1f) ? 1.0f : 0.0f);

                if (updrow[p] != 0) {
                    myact[nact++] = p;
                } else {
                    uint32_t ra = smb + SP_OFF + p*80;
                    float4* o4 = (float4*)(gdst + (size_t)p * NC);
                    #pragma unroll
                    for (int j = 0; j < 4; j++) {
                        u64 a, bb; lds_v2(ra + j*16, a, bb);
                        float2 f0 = upk2(a), f1 = upk2(bb);
                        o4[j] = make_float4(f0.x, f0.y, f1.x, f1.y);
                        if (j == 0) sts_f32(smb + ALN_OFF + p*4, f1.y);
                    }
                }
            }
            int pos = atomicAdd(cnt, nact);
            for (int i = 0; i < nact; i++) list[pos + i] = (unsigned short)myact[i];
        }
        __syncthreads();

        int A = cnt[0];

        if (A > 0) {
            // wave 1: inline clamp instead of list padding (no extra barrier)
            int i0 = 2*tid, i1 = 2*tid + 1;
            int p0 = (i0 < A) ? (int)list[i0] : (int)list[0];
            int p1 = (i1 < A) ? (int)list[i1] : (int)list[0];
            mlp_pixels<2>(smb, gdst, p0, p1);
            // tail: leftover (A > 768) as singles
            #pragma unroll 1
            for (int i = 2*NTHREADS + tid; i < A; i += NTHREADS)
                mlp_pixels<1>(smb, gdst, (int)list[i], (int)list[i]);
        }
        __syncthreads();

        // phase 2: alive mask on new alpha; finalize gdst + SP + AL + rgb.
        // Active pixels' pre-mask state loads hoisted above the 9-LDS max.
        for (int pix = tid; pix < HW; pix += NTHREADS) {
            bool act = (updrow[pix] != 0);
            uint32_t ra = smb + SP_OFF + pix*80;

            float4 g0, g1, g2, g3;
            if (act) {
                // issue early: L2 latency hidden under the alive-max chain
                const float4* g4 = (const float4*)(gdst + (size_t)pix * NC);
                g0 = g4[0]; g1 = g4[1]; g2 = g4[2]; g3 = g4[3];
            }

            int h = pix / WW, w = pix % WW;
            float m = -1e30f;
            #pragma unroll
            for (int dh = -1; dh <= 1; dh++) {
                int nh = h + dh;
                if ((unsigned)nh >= (unsigned)HH) continue;
                #pragma unroll
                for (int dw = -1; dw <= 1; dw++) {
                    int nw = w + dw;
                    if ((unsigned)nw >= (unsigned)WW) continue;
                    m = fmaxf(m, lds_f32(smb + ALN_OFF + (nh*WW + nw)*4));
                }
            }
            bool alive = (m >= 0.1f);

            float4 q0;
            if (alive) {
                if (act) {
                    q0 = g0;
                    sts_v4(ra,      g0);
                    sts_v4(ra + 16, g1);
                    sts_v4(ra + 32, g2);
                    sts_v4(ra + 48, g3);
                } else {
                    q0 = lds_v4f(ra);
                }
            } else {
                q0 = make_float4(0.f, 0.f, 0.f, 0.f);
                float4* o4 = (float4*)(gdst + (size_t)pix * NC);
                o4[0] = q0; o4[1] = q0; o4[2] = q0; o4[3] = q0;
                sts_v4(ra,      q0);
                sts_v4(ra + 16, q0);
                sts_v4(ra + 32, q0);
                sts_v4(ra + 48, q0);
            }
            sts_f32(smb + AL_OFF + pix*4, q0.w);
            if (rgb8 || rgbf)
                emit_rgb(r8, rf, (b*HW + pix)*3, q0.x, q0.y, q0.z, q0.w);
        }
        if (tid == 0) cnt[0] = 0;   // reset for next step, before the barrier
        __syncthreads();
    }
}

// ---------------- launch ----------------
extern "C" void kernel_launch(void* const* d_in, const int* in_sizes, int n_in,
                              void* d_out, int out_size) {
    const float* initial = (const float*)d_in[0];
    const float* W1 = (const float*)d_in[1];
    const float* b1 = (const float*)d_in[2];
    const float* W2 = (const float*)d_in[3];
    const int*  upd = (const int*)d_in[4];

    const long long NTOT = (long long)NFRAMES * NB * HW;
    const long long RGB_N = 3 * NTOT;
    const long long STK_N = 16 * NTOT;

    float* stacked = nullptr;
    unsigned char* rgb8 = nullptr;
    float* rgbf = nullptr;

    long long osz = (long long)out_size;
    if (osz >= RGB_N + 4*STK_N) {
        rgb8 = (unsigned char*)d_out;
        stacked = (float*)((char*)d_out + RGB_N);
    } else if (osz >= RGB_N + STK_N) {
        rgbf = (float*)d_out;
        stacked = (float*)d_out + RGB_N;
    } else if (osz >= STK_N) {
        stacked = (float*)d_out;
    } else if (osz >= RGB_N) {
        rgb8 = (unsigned char*)d_out;
    }

    float* stA = nullptr;
    float* stB = nullptr;
    if (!stacked) {
        cudaGetSymbolAddress((void**)&stA, g_stA);
        cudaGetSymbolAddress((void**)&stB, g_stB);
    }

    cudaFuncSetAttribute(nca_persist, cudaFuncAttributeMaxDynamicSharedMemorySize, SMEM_BYTES);

    nca_persist<<<NB, NTHREADS, SMEM_BYTES>>>(initial, stacked, stA, stB,
                                              W1, b1, W2, upd, rgb8, rgbf);
}